// round 1
// baseline (speedup 1.0000x reference)
#include <cuda_runtime.h>
#include <cstdint>

#define NN 8192
#define DD 128
#define NC 10
#define BM 64
#define BN 128

__device__ float g_x2[NN];
__device__ int   g_table[NC][16];
__device__ int   g_count[NC];

// ---------------------------------------------------------------------------
// Kernel 1: row norms + zero output
// ---------------------------------------------------------------------------
__global__ void bh_prep(const float* __restrict__ E, float* __restrict__ out)
{
    int r = blockIdx.x * blockDim.x + threadIdx.x;
    if (r == 0) out[0] = 0.0f;
    if (r < NN) {
        const float4* p = reinterpret_cast<const float4*>(E + (size_t)r * DD);
        float s = 0.f;
#pragma unroll
        for (int k = 0; k < DD / 4; k++) {
            float4 v = p[k];
            s += v.x * v.x + v.y * v.y + v.z * v.z + v.w * v.w;
        }
        g_x2[r] = s;
    }
}

// ---------------------------------------------------------------------------
// Kernel 2: per-class first-16 indices (in index order) + class counts.
// Single block, 256 threads, chunked two-pass scan over labels.
// ---------------------------------------------------------------------------
__global__ void bh_table(const int* __restrict__ labels)
{
    __shared__ int sl[NN];                 // 32 KB
    __shared__ int cnt[NC][256];           // 10 KB

    const int tid = threadIdx.x;
    for (int i = tid; i < NN; i += 256) sl[i] = labels[i];
    __syncthreads();

    const int base = tid * (NN / 256);     // 32 labels per thread
    int lc[NC];
#pragma unroll
    for (int c = 0; c < NC; c++) lc[c] = 0;
    for (int i = 0; i < NN / 256; i++) {
        int lbl = sl[base + i];
#pragma unroll
        for (int c = 0; c < NC; c++) lc[c] += (lbl == c);
    }
#pragma unroll
    for (int c = 0; c < NC; c++) cnt[c][tid] = lc[c];
    __syncthreads();

    // exclusive prefix per class (threads 0..9, sequential over 256 chunks)
    if (tid < NC) {
        int run = 0;
        for (int t = 0; t < 256; t++) {
            int tmp = cnt[tid][t];
            cnt[tid][t] = run;
            run += tmp;
        }
        g_count[tid] = run;
    }
    __syncthreads();

    // fill first-16 table
#pragma unroll
    for (int c = 0; c < NC; c++) {
        int b = cnt[c][tid];
        if (b < 16) {
            for (int i = 0; i < NN / 256; i++) {
                if (sl[base + i] == c) {
                    if (b < 16) g_table[c][b] = base + i;
                    b++;
                }
            }
        }
    }
}

// ---------------------------------------------------------------------------
// Kernel 3: main — 64 anchors per block vs all 8192 columns.
// ---------------------------------------------------------------------------
__global__ __launch_bounds__(256, 1)
void bh_main(const float* __restrict__ E, const int* __restrict__ labels,
             float* __restrict__ out)
{
    extern __shared__ float sm[];
    float* As  = sm;                       // [DD][BM]  k-major
    float* Bs  = As + DD * BM;             // [DD][BN]  k-major
    float* jx2 = Bs + DD * BN;             // [BN]
    float* ax2 = jx2 + BN;                 // [BM]
    int*   jl  = (int*)(ax2 + BM);         // [BN]
    int*   al  = jl + BN;                  // [BM]
    __shared__ float blockSum;

    const int tid  = threadIdx.x;
    const int tx   = tid & 15;             // 16 cols of 8
    const int ty   = tid >> 4;             // 16 rows of 4
    const int row0 = blockIdx.x * BM;

    if (tid == 0) blockSum = 0.f;

    // Load A tile transposed into SMEM (conflict-free stores; global reads
    // strided but L2-resident and one-time per block).
    for (int idx = tid; idx < BM * (DD / 4); idx += 256) {
        int r  = idx & (BM - 1);
        int k4 = idx >> 6;
        float4 v = *reinterpret_cast<const float4*>(E + (size_t)(row0 + r) * DD + k4 * 4);
        As[(k4 * 4 + 0) * BM + r] = v.x;
        As[(k4 * 4 + 1) * BM + r] = v.y;
        As[(k4 * 4 + 2) * BM + r] = v.z;
        As[(k4 * 4 + 3) * BM + r] = v.w;
    }
    if (tid < BM) { ax2[tid] = g_x2[row0 + tid]; al[tid] = labels[row0 + tid]; }

    float S[4][NC];
    float mp[4];
#pragma unroll
    for (int i = 0; i < 4; i++) {
        mp[i] = -1e30f;
#pragma unroll
        for (int c = 0; c < NC; c++) S[i][c] = 0.f;
    }

    for (int jt = 0; jt < NN; jt += BN) {
        __syncthreads();   // protect previous tile (and A-load on first iter)
        for (int idx = tid; idx < BN * (DD / 4); idx += 256) {
            int r  = idx & (BN - 1);
            int k4 = idx >> 7;
            float4 v = *reinterpret_cast<const float4*>(E + (size_t)(jt + r) * DD + k4 * 4);
            Bs[(k4 * 4 + 0) * BN + r] = v.x;
            Bs[(k4 * 4 + 1) * BN + r] = v.y;
            Bs[(k4 * 4 + 2) * BN + r] = v.z;
            Bs[(k4 * 4 + 3) * BN + r] = v.w;
        }
        if (tid < BN) { jx2[tid] = g_x2[jt + tid]; jl[tid] = labels[jt + tid]; }
        __syncthreads();

        float cacc[4][8];
#pragma unroll
        for (int i = 0; i < 4; i++)
#pragma unroll
            for (int j = 0; j < 8; j++) cacc[i][j] = 0.f;

#pragma unroll 8
        for (int k = 0; k < DD; k++) {
            float4 a  = *reinterpret_cast<const float4*>(&As[k * BM + ty * 4]);
            float4 b0 = *reinterpret_cast<const float4*>(&Bs[k * BN + tx * 8]);
            float4 b1 = *reinterpret_cast<const float4*>(&Bs[k * BN + tx * 8 + 4]);
            float av[4] = {a.x, a.y, a.z, a.w};
            float bv[8] = {b0.x, b0.y, b0.z, b0.w, b1.x, b1.y, b1.z, b1.w};
#pragma unroll
            for (int i = 0; i < 4; i++)
#pragma unroll
                for (int j = 0; j < 8; j++) cacc[i][j] += av[i] * bv[j];
        }

        // epilogue: clamp, same-class max, per-class sums
#pragma unroll
        for (int jj = 0; jj < 8; jj++) {
            int   col = tx * 8 + jj;
            int   lj  = jl[col];
            float xj  = jx2[col];
#pragma unroll
            for (int ii = 0; ii < 4; ii++) {
                float d = fmaxf(ax2[ty * 4 + ii] + xj - 2.0f * cacc[ii][jj], 0.0f);
                if (al[ty * 4 + ii] == lj) mp[ii] = fmaxf(mp[ii], d);
#pragma unroll
                for (int cc = 0; cc < NC; cc++)
                    S[ii][cc] += (lj == cc) ? d : 0.0f;
            }
        }
    }

    // reduce across the 16 tx threads (lanes 0..15 / 16..31 of each warp)
#pragma unroll
    for (int off = 8; off >= 1; off >>= 1) {
#pragma unroll
        for (int ii = 0; ii < 4; ii++) {
            mp[ii] = fmaxf(mp[ii], __shfl_down_sync(0xffffffffu, mp[ii], off, 16));
#pragma unroll
            for (int cc = 0; cc < NC; cc++)
                S[ii][cc] += __shfl_down_sync(0xffffffffu, S[ii][cc], off, 16);
        }
    }

    if (tx == 0) {
        float lsum = 0.f;
#pragma unroll
        for (int ii = 0; ii < 4; ii++) {
            int   a  = ty * 4 + ii;
            int   la = al[a];
            float T  = 0.f;
#pragma unroll
            for (int c = 0; c < NC; c++) T += S[ii][c];
            // argmin of neg_dist = T - S[c]  (first-min tie-break, matches jnp.argmin)
            float best = 3.4e38f;
            int   ks   = 0;
#pragma unroll
            for (int c = 0; c < NC; c++) {
                float nd = T - S[ii][c];
                if (nd < best) { best = nd; ks = c; }
            }
            // k_star-th negative in global (class, index) order
            int rem = ks, js = 0;
#pragma unroll
            for (int c = 0; c < NC; c++) {
                if (c == la) continue;
                int cn = g_count[c];
                if (rem < cn) { js = g_table[c][rem]; rem = 0x7fffffff; }
                else rem -= cn;
            }
            // recompute d(i, j_star) exactly in fp32
            const float4* p = reinterpret_cast<const float4*>(E + (size_t)js * DD);
            float dot = 0.f;
#pragma unroll
            for (int k4 = 0; k4 < DD / 4; k4++) {
                float4 v = p[k4];
                dot += As[(k4 * 4 + 0) * BM + a] * v.x;
                dot += As[(k4 * 4 + 1) * BM + a] * v.y;
                dot += As[(k4 * 4 + 2) * BM + a] * v.z;
                dot += As[(k4 * 4 + 3) * BM + a] * v.w;
            }
            float dn   = fmaxf(ax2[a] + g_x2[js] - 2.0f * dot, 0.0f);
            float loss = fmaxf(mp[ii] - dn + 1.0f, 0.0f);   // margin = 1.0
            lsum += loss;
        }
        atomicAdd(&blockSum, lsum);
    }
    __syncthreads();
    if (tid == 0) atomicAdd(out, blockSum * (1.0f / NN));
}

// ---------------------------------------------------------------------------
extern "C" void kernel_launch(void* const* d_in, const int* in_sizes, int n_in,
                              void* d_out, int out_size)
{
    const float* E      = (const float*)d_in[0];
    const int*   labels = (const int*)d_in[1];
    float*       out    = (float*)d_out;

    const int smem = (DD * BM + DD * BN + BN + BM) * 4 + (BN + BM) * 4;
    cudaFuncSetAttribute(bh_main, cudaFuncAttributeMaxDynamicSharedMemorySize, smem);

    bh_prep<<<NN / 256, 256>>>(E, out);
    bh_table<<<1, 256>>>(labels);
    bh_main<<<NN / BM, 256, smem>>>(E, labels, out);
}

// round 2
// speedup vs baseline: 1.6586x; 1.6586x over previous
#include <cuda_runtime.h>
#include <cstdint>

#define NN 8192
#define DD 128
#define NC 10
#define BM 128
#define BN 128
#define JSPLIT 2
#define JCHUNK (NN / JSPLIT)

__device__ float    g_x2[NN];
__device__ int      g_table[NC][16];
__device__ int      g_count[NC];
__device__ float    g_S[NN][NC];
__device__ unsigned g_mp[NN];

#define FFMA2(acc, a, b) \
    asm("fma.rn.f32x2 %0, %1, %2, %0;" : "+l"(acc) : "l"(a), "l"(b))
#define PACK2(dst, f) \
    asm("mov.b64 %0, {%1, %1};" : "=l"(dst) : "r"(__float_as_uint(f)))

// ---------------------------------------------------------------------------
// Kernel 1: row norms + zero g_S, g_mp, out
// ---------------------------------------------------------------------------
__global__ void bh_prep(const float* __restrict__ E, float* __restrict__ out)
{
    int r = blockIdx.x * blockDim.x + threadIdx.x;
    if (r == 0) out[0] = 0.0f;
    if (r < NN) {
        const float4* p = reinterpret_cast<const float4*>(E + (size_t)r * DD);
        float s = 0.f;
#pragma unroll
        for (int k = 0; k < DD / 4; k++) {
            float4 v = p[k];
            s += v.x * v.x + v.y * v.y + v.z * v.z + v.w * v.w;
        }
        g_x2[r] = s;
        g_mp[r] = 0u;
#pragma unroll
        for (int c = 0; c < NC; c++) g_S[r][c] = 0.f;
    }
}

// ---------------------------------------------------------------------------
// Kernel 2: per-class first-16 indices (index order) + class counts.
// ---------------------------------------------------------------------------
__global__ void bh_table(const int* __restrict__ labels)
{
    __shared__ int sl[NN];
    __shared__ int cnt[NC][256];

    const int tid = threadIdx.x;
    for (int i = tid; i < NN; i += 256) sl[i] = labels[i];
    __syncthreads();

    const int base = tid * (NN / 256);
    int lc[NC];
#pragma unroll
    for (int c = 0; c < NC; c++) lc[c] = 0;
    for (int i = 0; i < NN / 256; i++) {
        int lbl = sl[base + i];
#pragma unroll
        for (int c = 0; c < NC; c++) lc[c] += (lbl == c);
    }
#pragma unroll
    for (int c = 0; c < NC; c++) cnt[c][tid] = lc[c];
    __syncthreads();

    if (tid < NC) {
        int run = 0;
        for (int t = 0; t < 256; t++) { int tmp = cnt[tid][t]; cnt[tid][t] = run; run += tmp; }
        g_count[tid] = run;
    }
    __syncthreads();

#pragma unroll
    for (int c = 0; c < NC; c++) {
        int b = cnt[c][tid];
        if (b < 16) {
            for (int i = 0; i < NN / 256; i++) {
                if (sl[base + i] == c) {
                    if (b < 16) g_table[c][b] = base + i;
                    b++;
                }
            }
        }
    }
}

// ---------------------------------------------------------------------------
// Kernel 3: main Gram tile kernel. 128x128 tile per CTA, 8x8 micro-tile,
// packed f32x2 FMAs. Grid (64 row-blocks, 2 j-halves).
// Per-thread class sums live in SMEM slices (stride 81: conflict-free).
// ---------------------------------------------------------------------------
__global__ __launch_bounds__(256, 1)
void bh_main(const float* __restrict__ E, const int* __restrict__ labels)
{
    extern __shared__ float sm[];
    float* As  = sm;                    // [DD][BM] k-major
    float* Bs  = As + DD * BM;          // [DD][BN] k-major
    float* sS  = Bs + DD * BN;          // [256][81] per-thread S slices
    float* jx2 = sS + 256 * 81;         // [BN]
    int*   jl  = (int*)(jx2 + BN);      // [BN]

    const int tid  = threadIdx.x;
    const int tx   = tid & 15;          // column group (8 cols)
    const int ty   = tid >> 4;          // row group (8 rows)
    const int row0 = blockIdx.x * BM;
    const int j0   = blockIdx.y * JCHUNK;

    // zero my S slice
#pragma unroll
    for (int i = 0; i < 81; i++) sS[tid * 81 + i] = 0.f;

    // load A tile transposed (k-major), coalesced global, conflict-free stores
    for (int idx = tid; idx < BM * (DD / 4); idx += 256) {
        int r  = idx & (BM - 1);
        int k4 = idx >> 7;
        float4 v = *reinterpret_cast<const float4*>(E + (size_t)(row0 + r) * DD + k4 * 4);
        As[(k4 * 4 + 0) * BM + r] = v.x;
        As[(k4 * 4 + 1) * BM + r] = v.y;
        As[(k4 * 4 + 2) * BM + r] = v.z;
        As[(k4 * 4 + 3) * BM + r] = v.w;
    }

    float ax[8];
    int   myl[8];
#pragma unroll
    for (int ii = 0; ii < 8; ii++) {
        ax[ii]  = g_x2[row0 + ty * 8 + ii];
        myl[ii] = labels[row0 + ty * 8 + ii];
    }
    float mp[8];
#pragma unroll
    for (int ii = 0; ii < 8; ii++) mp[ii] = 0.f;   // d >= 0 and self included

    for (int t = 0; t < JCHUNK / BN; t++) {
        __syncthreads();
        const int jb = j0 + t * BN;
        for (int idx = tid; idx < BN * (DD / 4); idx += 256) {
            int r  = idx & (BN - 1);
            int k4 = idx >> 7;
            float4 v = *reinterpret_cast<const float4*>(E + (size_t)(jb + r) * DD + k4 * 4);
            Bs[(k4 * 4 + 0) * BN + r] = v.x;
            Bs[(k4 * 4 + 1) * BN + r] = v.y;
            Bs[(k4 * 4 + 2) * BN + r] = v.z;
            Bs[(k4 * 4 + 3) * BN + r] = v.w;
        }
        if (tid < BN) { jx2[tid] = g_x2[jb + tid]; jl[tid] = labels[jb + tid]; }
        __syncthreads();

        unsigned long long acc[4][8];
#pragma unroll
        for (int ip = 0; ip < 4; ip++)
#pragma unroll
            for (int j = 0; j < 8; j++) acc[ip][j] = 0ull;

#pragma unroll 4
        for (int k = 0; k < DD; k++) {
            ulonglong2 a01 = *reinterpret_cast<const ulonglong2*>(&As[k * BM + ty * 8]);
            ulonglong2 a23 = *reinterpret_cast<const ulonglong2*>(&As[k * BM + ty * 8 + 4]);
            float4 b0 = *reinterpret_cast<const float4*>(&Bs[k * BN + tx * 8]);
            float4 b1 = *reinterpret_cast<const float4*>(&Bs[k * BN + tx * 8 + 4]);
            unsigned long long av[4] = {a01.x, a01.y, a23.x, a23.y};
            unsigned long long bb[8];
            PACK2(bb[0], b0.x); PACK2(bb[1], b0.y); PACK2(bb[2], b0.z); PACK2(bb[3], b0.w);
            PACK2(bb[4], b1.x); PACK2(bb[5], b1.y); PACK2(bb[6], b1.z); PACK2(bb[7], b1.w);
#pragma unroll
            for (int ip = 0; ip < 4; ip++)
#pragma unroll
                for (int j = 0; j < 8; j++)
                    FFMA2(acc[ip][j], av[ip], bb[j]);
        }

        // epilogue: d = max(ax + xj - 2*dot, 0); same-class max; class sums
#pragma unroll
        for (int jj = 0; jj < 8; jj++) {
            const int   col = tx * 8 + jj;
            const int   lj  = jl[col];
            const float xj  = jx2[col];
            float* slot = &sS[tid * 81 + lj];
#pragma unroll
            for (int ip = 0; ip < 4; ip++) {
                unsigned long long p = acc[ip][jj];
                float lo = __uint_as_float((unsigned)(p & 0xffffffffu));
                float hi = __uint_as_float((unsigned)(p >> 32));
                int   i0 = ip * 2, i1 = ip * 2 + 1;
                float d0 = fmaxf(fmaf(-2.0f, lo, ax[i0] + xj), 0.0f);
                float d1 = fmaxf(fmaf(-2.0f, hi, ax[i1] + xj), 0.0f);
                if (myl[i0] == lj) mp[i0] = fmaxf(mp[i0], d0);
                if (myl[i1] == lj) mp[i1] = fmaxf(mp[i1], d1);
                slot[i0 * 10] += d0;
                slot[i1 * 10] += d1;
            }
        }
    }
    __syncthreads();

    // mp: reduce across tx (lanes 0..15 / 16..31 within warp), publish
#pragma unroll
    for (int off = 8; off >= 1; off >>= 1)
#pragma unroll
        for (int ii = 0; ii < 8; ii++)
            mp[ii] = fmaxf(mp[ii], __shfl_down_sync(0xffffffffu, mp[ii], off, 16));
    if (tx == 0) {
#pragma unroll
        for (int ii = 0; ii < 8; ii++)
            atomicMax(&g_mp[row0 + ty * 8 + ii], __float_as_uint(mp[ii]));
    }

    // S: reduce 16 tx slices per (row, class), publish. 1280 cells / 256 thr = 5.
#pragma unroll
    for (int p = 0; p < 5; p++) {
        int cell = tid * 5 + p;          // 0..1279
        int row  = cell / NC;            // 0..127
        int c    = cell - row * NC;
        int ryt  = row >> 3, rii = row & 7;
        float s = 0.f;
#pragma unroll
        for (int xx = 0; xx < 16; xx++)
            s += sS[(ryt * 16 + xx) * 81 + rii * 10 + c];
        atomicAdd(&g_S[row0 + row][c], s);
    }
}

// ---------------------------------------------------------------------------
// Kernel 4: finalize — per-anchor argmin, table walk, exact d_neg, loss.
// ---------------------------------------------------------------------------
__global__ void bh_final(const float* __restrict__ E, const int* __restrict__ labels,
                         float* __restrict__ out)
{
    const int i = blockIdx.x * blockDim.x + threadIdx.x;

    float T = 0.f, S[NC];
#pragma unroll
    for (int c = 0; c < NC; c++) { S[c] = g_S[i][c]; T += S[c]; }

    float best = 3.4e38f;
    int   ks   = 0;
#pragma unroll
    for (int c = 0; c < NC; c++) {
        float nd = T - S[c];
        if (nd < best) { best = nd; ks = c; }
    }

    const int la = labels[i];
    int rem = ks, js = 0;
#pragma unroll
    for (int c = 0; c < NC; c++) {
        if (c == la) continue;
        int cn = g_count[c];
        if (rem < cn) { js = g_table[c][rem]; rem = 0x7fffffff; }
        else rem -= cn;
    }

    const float4* pa = reinterpret_cast<const float4*>(E + (size_t)i * DD);
    const float4* pb = reinterpret_cast<const float4*>(E + (size_t)js * DD);
    float dot = 0.f;
#pragma unroll
    for (int k = 0; k < DD / 4; k++) {
        float4 a = pa[k], b = pb[k];
        dot += a.x * b.x + a.y * b.y + a.z * b.z + a.w * b.w;
    }
    float dn   = fmaxf(g_x2[i] + g_x2[js] - 2.0f * dot, 0.0f);
    float loss = fmaxf(__uint_as_float(g_mp[i]) - dn + 1.0f, 0.0f);

    // warp then block reduce
#pragma unroll
    for (int off = 16; off >= 1; off >>= 1)
        loss += __shfl_down_sync(0xffffffffu, loss, off);
    __shared__ float wsum[8];
    if ((threadIdx.x & 31) == 0) wsum[threadIdx.x >> 5] = loss;
    __syncthreads();
    if (threadIdx.x == 0) {
        float s = 0.f;
#pragma unroll
        for (int w = 0; w < 8; w++) s += wsum[w];
        atomicAdd(out, s * (1.0f / NN));
    }
}

// ---------------------------------------------------------------------------
extern "C" void kernel_launch(void* const* d_in, const int* in_sizes, int n_in,
                              void* d_out, int out_size)
{
    const float* E      = (const float*)d_in[0];
    const int*   labels = (const int*)d_in[1];
    float*       out    = (float*)d_out;

    const int smem = (DD * BM + DD * BN + 256 * 81 + BN) * 4 + BN * 4;
    cudaFuncSetAttribute(bh_main, cudaFuncAttributeMaxDynamicSharedMemorySize, smem);

    bh_prep<<<NN / 256, 256>>>(E, out);
    bh_table<<<1, 256>>>(labels);
    bh_main<<<dim3(NN / BM, JSPLIT), 256, smem>>>(E, labels);
    bh_final<<<NN / 256, 256>>>(E, labels, out);
}